// round 10
// baseline (speedup 1.0000x reference)
#include <cuda_runtime.h>
#include <cuda_bf16.h>
#include <cstdint>

#define D 128
#define MAX_NODES 100000
#define MAX_EDGES 1600000

// ---- scratch (__device__ globals; no allocs allowed) ----
__device__ float4 g_x4[MAX_NODES * (D / 4)];     // x = ego + side, 51.2 MB
__device__ uint2  g_edges[MAX_EDGES];            // per-node {src, w-bits}, 12.8 MB
__device__ int    g_counts[MAX_NODES];
__device__ int    g_offsets[MAX_NODES];
__device__ int    g_cursor[MAX_NODES];
__device__ int    g_total;
__device__ int    g_idx_is32;

// ---------------------------------------------------------------------------
// K0: detect edge_index dtype. int64 indices < 1e5 -> high word always 0.
// Any nonzero high word in 64 samples => buffer is int32 pairs.
// ---------------------------------------------------------------------------
__global__ void detect_idx_dtype_kernel(const unsigned long long* __restrict__ ei,
                                        int n_samples) {
    if (threadIdx.x == 0) {
        int saw_high = 0;
        for (int i = 0; i < n_samples; i++)
            if (ei[i] >> 32) { saw_high = 1; break; }
        g_idx_is32 = saw_high;
    }
}

// K1: zero counts + total
__global__ void zero_counts_kernel(int n_nodes) {
    int i = blockIdx.x * blockDim.x + threadIdx.x;
    if (i < n_nodes) g_counts[i] = 0;
    if (i == 0) g_total = 0;
}

// K2: histogram of dst degrees
__global__ void count_kernel(const void* __restrict__ ei, int n_edges, int n_nodes) {
    int e = blockIdx.x * blockDim.x + threadIdx.x;
    if (e >= n_edges) return;
    long long dst = g_idx_is32 ? (long long)((const int*)ei)[e]
                               : ((const long long*)ei)[e];
    if ((unsigned long long)dst < (unsigned long long)n_nodes)
        atomicAdd(&g_counts[dst], 1);
}

// K3: per-node segment offsets. Block-local scan + one global atomicAdd per
// block for the base (segment disjointness is order-independent).
__global__ void offsets_kernel(int n_nodes) {
    __shared__ int warp_sums[32];
    __shared__ int block_base;
    int i = blockIdx.x * 1024 + threadIdx.x;
    int lane = threadIdx.x & 31, wid = threadIdx.x >> 5;

    int c = (i < n_nodes) ? g_counts[i] : 0;
    int x = c;
    #pragma unroll
    for (int d = 1; d < 32; d <<= 1) {
        int y = __shfl_up_sync(0xFFFFFFFFu, x, d);
        if (lane >= d) x += y;
    }
    if (lane == 31) warp_sums[wid] = x;
    __syncthreads();
    if (wid == 0) {
        int s = warp_sums[lane];
        #pragma unroll
        for (int d = 1; d < 32; d <<= 1) {
            int y = __shfl_up_sync(0xFFFFFFFFu, s, d);
            if (lane >= d) s += y;
        }
        warp_sums[lane] = s;
        if (lane == 31) block_base = atomicAdd(&g_total, s);
    }
    __syncthreads();
    int warp_base = (wid > 0) ? warp_sums[wid - 1] : 0;
    int excl = block_base + warp_base + (x - c);
    if (i < n_nodes) { g_offsets[i] = excl; g_cursor[i] = excl; }
}

// K4: scatter edges into per-node segments
__global__ void fill_kernel(const void* __restrict__ ei,
                            const float* __restrict__ ew,
                            int n_edges, int n_nodes) {
    int e = blockIdx.x * blockDim.x + threadIdx.x;
    if (e >= n_edges) return;
    long long dst, src;
    if (g_idx_is32) {
        dst = (long long)((const int*)ei)[e];
        src = (long long)((const int*)ei)[n_edges + e];
    } else {
        dst = ((const long long*)ei)[e];
        src = ((const long long*)ei)[n_edges + e];
    }
    if ((unsigned long long)dst >= (unsigned long long)n_nodes ||
        (unsigned long long)src >= (unsigned long long)n_nodes) return;
    int pos = atomicAdd(&g_cursor[dst], 1);
    if (pos < MAX_EDGES)
        g_edges[pos] = make_uint2((unsigned)src, __float_as_uint(ew[e]));
}

// K5: gather-aggregate. One warp per node: x[v] = ego[v] + sum w_e*ego[src_e]
__global__ __launch_bounds__(256)
void aggregate_kernel(const float4* __restrict__ ego4, int n_nodes) {
    int warp = (blockIdx.x * blockDim.x + threadIdx.x) >> 5;
    int lane = threadIdx.x & 31;
    if (warp >= n_nodes) return;

    int off = g_offsets[warp];
    int deg = g_counts[warp];

    float4 acc = ego4[(long)warp * (D / 4) + lane];

    int e = 0;
    for (; e + 4 <= deg; e += 4) {
        uint2 p0 = g_edges[off + e + 0];
        uint2 p1 = g_edges[off + e + 1];
        uint2 p2 = g_edges[off + e + 2];
        uint2 p3 = g_edges[off + e + 3];
        float4 r0 = ego4[(long)p0.x * (D / 4) + lane];
        float4 r1 = ego4[(long)p1.x * (D / 4) + lane];
        float4 r2 = ego4[(long)p2.x * (D / 4) + lane];
        float4 r3 = ego4[(long)p3.x * (D / 4) + lane];
        float w0 = __uint_as_float(p0.y), w1 = __uint_as_float(p1.y);
        float w2 = __uint_as_float(p2.y), w3 = __uint_as_float(p3.y);
        acc.x += r0.x * w0 + r1.x * w1 + r2.x * w2 + r3.x * w3;
        acc.y += r0.y * w0 + r1.y * w1 + r2.y * w2 + r3.y * w3;
        acc.z += r0.z * w0 + r1.z * w1 + r2.z * w2 + r3.z * w3;
        acc.w += r0.w * w0 + r1.w * w1 + r2.w * w2 + r3.w * w3;
    }
    for (; e < deg; e++) {
        uint2 p = g_edges[off + e];
        float4 r = ego4[(long)p.x * (D / 4) + lane];
        float w = __uint_as_float(p.y);
        acc.x += r.x * w; acc.y += r.y * w; acc.z += r.z * w; acc.w += r.w * w;
    }
    g_x4[(long)warp * (D / 4) + lane] = acc;
}

// ---------------------------------------------------------------------------
// K6: out = LeakyReLU(x @ W^T + b) via TF32 tensor cores (3-pass hi/lo split).
// Block 256 thr: 128x128 output tile. Warp w: rows [w*16, w*16+16), all 128 cols.
// mma.sync.m16n8k8.row.col. W pre-swizzled in smem in fragment order,
// lane stride 36 floats -> conflict-free lds.128 B-fragment loads.
// ---------------------------------------------------------------------------
#define XS_STRIDE 132   // x tile row stride (conflict-free A-frag lds.32)
#define WF_STRIDE 36    // per-(ntile,lane) stride in fragment-order W

__device__ __forceinline__ void mma_tf32(float* c, const unsigned* a,
                                         unsigned b0, unsigned b1) {
    asm volatile(
        "mma.sync.aligned.m16n8k8.row.col.f32.tf32.tf32.f32 "
        "{%0,%1,%2,%3}, {%4,%5,%6,%7}, {%8,%9}, {%0,%1,%2,%3};"
        : "+f"(c[0]), "+f"(c[1]), "+f"(c[2]), "+f"(c[3])
        : "r"(a[0]), "r"(a[1]), "r"(a[2]), "r"(a[3]), "r"(b0), "r"(b1));
}

__device__ __forceinline__ unsigned to_tf32(float f) {
    unsigned u;
    asm("cvt.rna.tf32.f32 %0, %1;" : "=r"(u) : "f"(f));
    return u;
}

__global__ __launch_bounds__(256, 1)
void gemm_tf32_kernel(const float* __restrict__ W,
                      const float* __restrict__ b,
                      float* __restrict__ out, int n_nodes) {
    extern __shared__ float sm[];
    float* xs = sm;                       // [128][XS_STRIDE]
    float* wf = xs + 128 * XS_STRIDE;     // [16 ntiles][32 lanes][WF_STRIDE]
    float* bs = wf + 16 * 32 * WF_STRIDE; // [128]

    int tid = threadIdx.x;
    int lane = tid & 31, wid = tid >> 5;
    int row0 = blockIdx.x * 128;

    // Stage W into fragment order:
    // wf[(t*32+l)*36 + kt*2 + j] = W[t*8 + (l>>2)][kt*8 + (l&3) + 4*j]
    for (int idx = tid; idx < 16384; idx += 256) {
        int t = idx >> 10;
        int rem = idx & 1023;
        int l = rem >> 5;
        int q = rem & 31;
        int kt = q >> 1, j = q & 1;
        int n = t * 8 + (l >> 2);
        int k = kt * 8 + (l & 3) + 4 * j;
        wf[(t * 32 + l) * WF_STRIDE + kt * 2 + j] = W[n * D + k];
    }
    if (tid < D) bs[tid] = b[tid];

    // Stage x tile (float4, zero-pad tail rows)
    for (int idx = tid; idx < 128 * 32; idx += 256) {
        int r = idx >> 5, c4 = idx & 31;
        int row = row0 + r;
        float4 v = (row < n_nodes) ? g_x4[(long)row * 32 + c4]
                                   : make_float4(0.f, 0.f, 0.f, 0.f);
        *reinterpret_cast<float4*>(&xs[r * XS_STRIDE + c4 * 4]) = v;
    }
    __syncthreads();

    float acc[16][4];
    #pragma unroll
    for (int t = 0; t < 16; t++)
        #pragma unroll
        for (int i = 0; i < 4; i++) acc[t][i] = 0.f;

    int m0 = wid * 16;

    #pragma unroll
    for (int kh = 0; kh < 2; kh++) {
        // A fragments for 8 k-tiles, hi/lo split, register-resident.
        unsigned ahi[8][4], alo[8][4];
        #pragma unroll
        for (int kt8 = 0; kt8 < 8; kt8++) {
            int kt = kh * 8 + kt8;
            #pragma unroll
            for (int i = 0; i < 4; i++) {
                int r = m0 + (lane >> 2) + (i & 1) * 8;
                int c = kt * 8 + (lane & 3) + (i >> 1) * 4;
                float f = xs[r * XS_STRIDE + c];
                unsigned h = to_tf32(f);
                ahi[kt8][i] = h;
                alo[kt8][i] = to_tf32(f - __uint_as_float(h));
            }
        }
        #pragma unroll
        for (int t = 0; t < 16; t++) {
            const float* wrow = wf + (t * 32 + lane) * WF_STRIDE + kh * 16;
            #pragma unroll
            for (int p = 0; p < 4; p++) {         // each p = 2 k-tiles
                float4 v = *reinterpret_cast<const float4*>(wrow + p * 4);
                float vals[4] = {v.x, v.y, v.z, v.w};
                #pragma unroll
                for (int q2 = 0; q2 < 2; q2++) {
                    int kt8 = p * 2 + q2;
                    float b0f = vals[q2 * 2], b1f = vals[q2 * 2 + 1];
                    unsigned b0h = to_tf32(b0f);
                    unsigned b0l = to_tf32(b0f - __uint_as_float(b0h));
                    unsigned b1h = to_tf32(b1f);
                    unsigned b1l = to_tf32(b1f - __uint_as_float(b1h));
                    mma_tf32(acc[t], ahi[kt8], b0h, b1h);   // hi*hi
                    mma_tf32(acc[t], ahi[kt8], b0l, b1l);   // hi*lo
                    mma_tf32(acc[t], alo[kt8], b0h, b1h);   // lo*hi
                }
            }
        }
    }

    // Epilogue: bias + LeakyReLU, st.v2 per acc row-pair
    int r0 = row0 + m0 + (lane >> 2);
    #pragma unroll
    for (int t = 0; t < 16; t++) {
        int col = t * 8 + 2 * (lane & 3);
        float bb0 = bs[col], bb1 = bs[col + 1];
        float v0 = acc[t][0] + bb0, v1 = acc[t][1] + bb1;
        float v2 = acc[t][2] + bb0, v3 = acc[t][3] + bb1;
        v0 = v0 > 0.f ? v0 : 0.01f * v0;
        v1 = v1 > 0.f ? v1 : 0.01f * v1;
        v2 = v2 > 0.f ? v2 : 0.01f * v2;
        v3 = v3 > 0.f ? v3 : 0.01f * v3;
        if (r0 < n_nodes)
            *reinterpret_cast<float2*>(out + (long)r0 * D + col) = make_float2(v0, v1);
        if (r0 + 8 < n_nodes)
            *reinterpret_cast<float2*>(out + (long)(r0 + 8) * D + col) = make_float2(v2, v3);
    }
}

// ---------------------------------------------------------------------------
extern "C" void kernel_launch(void* const* d_in, const int* in_sizes, int n_in,
                              void* d_out, int out_size) {
    const float* ego = (const float*)d_in[0];
    const void*  ei  = d_in[1];
    const float* ew  = (const float*)d_in[2];
    const float* W   = (const float*)d_in[3];
    const float* b   = (const float*)d_in[4];
    float*       out = (float*)d_out;

    int n_nodes = in_sizes[0] / D;
    int n_edges = in_sizes[2];
    if (n_edges > MAX_EDGES) n_edges = MAX_EDGES;

    int n_samples = n_edges < 64 ? n_edges : 64;
    detect_idx_dtype_kernel<<<1, 32>>>((const unsigned long long*)ei, n_samples);

    zero_counts_kernel<<<(n_nodes + 255) / 256, 256>>>(n_nodes);
    count_kernel<<<(n_edges + 255) / 256, 256>>>(ei, n_edges, n_nodes);
    offsets_kernel<<<(n_nodes + 1023) / 1024, 1024>>>(n_nodes);
    fill_kernel<<<(n_edges + 255) / 256, 256>>>(ei, ew, n_edges, n_nodes);

    aggregate_kernel<<<(n_nodes + 7) / 8, 256>>>((const float4*)ego, n_nodes);

    size_t smem = (128 * XS_STRIDE + 16 * 32 * WF_STRIDE + D) * sizeof(float); // ~139 KB
    cudaFuncSetAttribute(gemm_tf32_kernel,
                         cudaFuncAttributeMaxDynamicSharedMemorySize, (int)smem);
    gemm_tf32_kernel<<<(n_nodes + 127) / 128, 256, smem>>>(W, b, out, n_nodes);
}

// round 11
// speedup vs baseline: 1.1686x; 1.1686x over previous
#include <cuda_runtime.h>
#include <cuda_bf16.h>
#include <cstdint>

#define D 128
#define MAX_NODES 100000
#define MAX_EDGES 1600000

// ---- scratch (__device__ globals; no allocs allowed) ----
// x = ego + side, pre-split into packed bf16 hi / lo pairs (k-pairs in u32).
__device__ uint2  g_xhi[MAX_NODES * 32];         // 25.6 MB
__device__ uint2  g_xlo[MAX_NODES * 32];         // 25.6 MB
__device__ uint2  g_edges[MAX_EDGES];            // per-node {src, w-bits}, 12.8 MB
__device__ int    g_counts[MAX_NODES];
__device__ int    g_offsets[MAX_NODES];
__device__ int    g_cursor[MAX_NODES];
__device__ int    g_total;
__device__ int    g_idx_is32;

// ---------------------------------------------------------------------------
// K0: detect edge_index dtype. int64 indices < 1e5 -> high word always 0.
// Any nonzero high word in 64 samples => buffer is int32 pairs.
// ---------------------------------------------------------------------------
__global__ void detect_idx_dtype_kernel(const unsigned long long* __restrict__ ei,
                                        int n_samples) {
    if (threadIdx.x == 0) {
        int saw_high = 0;
        for (int i = 0; i < n_samples; i++)
            if (ei[i] >> 32) { saw_high = 1; break; }
        g_idx_is32 = saw_high;
    }
}

// K1: zero counts + total
__global__ void zero_counts_kernel(int n_nodes) {
    int i = blockIdx.x * blockDim.x + threadIdx.x;
    if (i < n_nodes) g_counts[i] = 0;
    if (i == 0) g_total = 0;
}

// K2: histogram of dst degrees
__global__ void count_kernel(const void* __restrict__ ei, int n_edges, int n_nodes) {
    int e = blockIdx.x * blockDim.x + threadIdx.x;
    if (e >= n_edges) return;
    long long dst = g_idx_is32 ? (long long)((const int*)ei)[e]
                               : ((const long long*)ei)[e];
    if ((unsigned long long)dst < (unsigned long long)n_nodes)
        atomicAdd(&g_counts[dst], 1);
}

// K3: per-node segment offsets. Block-local scan + one global atomicAdd per
// block for the base (segment disjointness is order-independent).
__global__ void offsets_kernel(int n_nodes) {
    __shared__ int warp_sums[32];
    __shared__ int block_base;
    int i = blockIdx.x * 1024 + threadIdx.x;
    int lane = threadIdx.x & 31, wid = threadIdx.x >> 5;

    int c = (i < n_nodes) ? g_counts[i] : 0;
    int x = c;
    #pragma unroll
    for (int d = 1; d < 32; d <<= 1) {
        int y = __shfl_up_sync(0xFFFFFFFFu, x, d);
        if (lane >= d) x += y;
    }
    if (lane == 31) warp_sums[wid] = x;
    __syncthreads();
    if (wid == 0) {
        int s = warp_sums[lane];
        #pragma unroll
        for (int d = 1; d < 32; d <<= 1) {
            int y = __shfl_up_sync(0xFFFFFFFFu, s, d);
            if (lane >= d) s += y;
        }
        warp_sums[lane] = s;
        if (lane == 31) block_base = atomicAdd(&g_total, s);
    }
    __syncthreads();
    int warp_base = (wid > 0) ? warp_sums[wid - 1] : 0;
    int excl = block_base + warp_base + (x - c);
    if (i < n_nodes) { g_offsets[i] = excl; g_cursor[i] = excl; }
}

// K4: scatter edges into per-node segments
__global__ void fill_kernel(const void* __restrict__ ei,
                            const float* __restrict__ ew,
                            int n_edges, int n_nodes) {
    int e = blockIdx.x * blockDim.x + threadIdx.x;
    if (e >= n_edges) return;
    long long dst, src;
    if (g_idx_is32) {
        dst = (long long)((const int*)ei)[e];
        src = (long long)((const int*)ei)[n_edges + e];
    } else {
        dst = ((const long long*)ei)[e];
        src = ((const long long*)ei)[n_edges + e];
    }
    if ((unsigned long long)dst >= (unsigned long long)n_nodes ||
        (unsigned long long)src >= (unsigned long long)n_nodes) return;
    int pos = atomicAdd(&g_cursor[dst], 1);
    if (pos < MAX_EDGES)
        g_edges[pos] = make_uint2((unsigned)src, __float_as_uint(ew[e]));
}

// ---------------------------------------------------------------------------
// K5: gather-aggregate + bf16 hi/lo split emit.
//   x[v] = ego[v] + sum w_e*ego[src_e];  g_xhi/g_xlo = packed bf16 pairs.
// ---------------------------------------------------------------------------
__device__ __forceinline__ unsigned pack_bf16(float a, float b) {
    __nv_bfloat162 t = __floats2bfloat162_rn(a, b);   // .x = a (low half)
    return *reinterpret_cast<unsigned*>(&t);
}

__global__ __launch_bounds__(256)
void aggregate_kernel(const float4* __restrict__ ego4, int n_nodes) {
    int warp = (blockIdx.x * blockDim.x + threadIdx.x) >> 5;
    int lane = threadIdx.x & 31;
    if (warp >= n_nodes) return;

    int off = g_offsets[warp];
    int deg = g_counts[warp];

    float4 acc = ego4[(long)warp * (D / 4) + lane];

    int e = 0;
    for (; e + 4 <= deg; e += 4) {
        uint2 p0 = g_edges[off + e + 0];
        uint2 p1 = g_edges[off + e + 1];
        uint2 p2 = g_edges[off + e + 2];
        uint2 p3 = g_edges[off + e + 3];
        float4 r0 = ego4[(long)p0.x * (D / 4) + lane];
        float4 r1 = ego4[(long)p1.x * (D / 4) + lane];
        float4 r2 = ego4[(long)p2.x * (D / 4) + lane];
        float4 r3 = ego4[(long)p3.x * (D / 4) + lane];
        float w0 = __uint_as_float(p0.y), w1 = __uint_as_float(p1.y);
        float w2 = __uint_as_float(p2.y), w3 = __uint_as_float(p3.y);
        acc.x += r0.x * w0 + r1.x * w1 + r2.x * w2 + r3.x * w3;
        acc.y += r0.y * w0 + r1.y * w1 + r2.y * w2 + r3.y * w3;
        acc.z += r0.z * w0 + r1.z * w1 + r2.z * w2 + r3.z * w3;
        acc.w += r0.w * w0 + r1.w * w1 + r2.w * w2 + r3.w * w3;
    }
    for (; e < deg; e++) {
        uint2 p = g_edges[off + e];
        float4 r = ego4[(long)p.x * (D / 4) + lane];
        float w = __uint_as_float(p.y);
        acc.x += r.x * w; acc.y += r.y * w; acc.z += r.z * w; acc.w += r.w * w;
    }

    // hi/lo split (hi = bf16 round, lo = bf16(residual))
    __nv_bfloat162 h01 = __floats2bfloat162_rn(acc.x, acc.y);
    __nv_bfloat162 h23 = __floats2bfloat162_rn(acc.z, acc.w);
    float lx = acc.x - __bfloat162float(h01.x);
    float ly = acc.y - __bfloat162float(h01.y);
    float lz = acc.z - __bfloat162float(h23.x);
    float lw = acc.w - __bfloat162float(h23.y);

    g_xhi[(long)warp * 32 + lane] =
        make_uint2(*reinterpret_cast<unsigned*>(&h01), *reinterpret_cast<unsigned*>(&h23));
    g_xlo[(long)warp * 32 + lane] = make_uint2(pack_bf16(lx, ly), pack_bf16(lz, lw));
}

// ---------------------------------------------------------------------------
// K6: out = LeakyReLU(x @ W^T + b) via bf16 tensor cores, 3-pass hi/lo split.
// Block 256 thr, BM=64 x BN=128 tile. Warp grid 4(m) x 2(n): warp = 16 rows x
// 64 cols = 8 n-tiles. mma.m16n8k16.row.col. All cvt hoisted: A from
// pre-split g_xhi/g_xlo; W fragments packed once into uint4 table ->
// mainloop = pure LDS + HMMA.
// ---------------------------------------------------------------------------
#define XS_STRIDE 68   // u32 (k-pair) stride: bank = 4*row + pair -> conflict-free

__device__ __forceinline__ void mma_bf16(float* c, const unsigned* a,
                                         unsigned b0, unsigned b1) {
    asm volatile(
        "mma.sync.aligned.m16n8k16.row.col.f32.bf16.bf16.f32 "
        "{%0,%1,%2,%3}, {%4,%5,%6,%7}, {%8,%9}, {%0,%1,%2,%3};"
        : "+f"(c[0]), "+f"(c[1]), "+f"(c[2]), "+f"(c[3])
        : "r"(a[0]), "r"(a[1]), "r"(a[2]), "r"(a[3]), "r"(b0), "r"(b1));
}

__global__ __launch_bounds__(256, 2)
void gemm_bf16_kernel(const float* __restrict__ W,
                      const float* __restrict__ b,
                      float* __restrict__ out, int n_nodes) {
    extern __shared__ unsigned smu[];
    uint4*    wf    = reinterpret_cast<uint4*>(smu);       // [16 t][8 kt][32 lane] {hi01,hi89,lo01,lo89}
    unsigned* xs_hi = smu + 16384;                         // [64][XS_STRIDE] k-pair u32
    unsigned* xs_lo = xs_hi + 64 * XS_STRIDE;
    float*    bs    = reinterpret_cast<float*>(xs_lo + 64 * XS_STRIDE);  // [128]

    int tid = threadIdx.x;
    int lane = tid & 31, wid = tid >> 5;
    int row0 = blockIdx.x * 64;

    // ---- stage W fragments (hi/lo packed, fragment order) ----
    // entry e -> t = e>>8, kt = (e>>5)&7, l = e&31
    // n = t*8 + (l>>2); k0 = kt*16 + (l&3)*2; pairs {k0,k0+1} and {k0+8,k0+9}
    for (int e = tid; e < 4096; e += 256) {
        int t = e >> 8, kt = (e >> 5) & 7, l = e & 31;
        int n = t * 8 + (l >> 2);
        int k0 = kt * 16 + (l & 3) * 2;
        const float* wr = W + n * D + k0;
        float f0 = wr[0], f1 = wr[1], f8 = wr[8], f9 = wr[9];
        __nv_bfloat162 h01 = __floats2bfloat162_rn(f0, f1);
        __nv_bfloat162 h89 = __floats2bfloat162_rn(f8, f9);
        unsigned hi01 = *reinterpret_cast<unsigned*>(&h01);
        unsigned hi89 = *reinterpret_cast<unsigned*>(&h89);
        unsigned lo01 = pack_bf16(f0 - __bfloat162float(h01.x), f1 - __bfloat162float(h01.y));
        unsigned lo89 = pack_bf16(f8 - __bfloat162float(h89.x), f9 - __bfloat162float(h89.y));
        wf[e] = make_uint4(hi01, hi89, lo01, lo89);
    }
    if (tid < D) bs[tid] = b[tid];

    // ---- stage x tile (pre-split pairs; zero-pad tail rows) ----
    for (int idx = tid; idx < 64 * 32; idx += 256) {
        int r = idx >> 5, l = idx & 31;
        int row = row0 + r;
        uint2 vh = make_uint2(0u, 0u), vl = make_uint2(0u, 0u);
        if (row < n_nodes) {
            vh = g_xhi[(long)row * 32 + l];
            vl = g_xlo[(long)row * 32 + l];
        }
        xs_hi[r * XS_STRIDE + 2 * l]     = vh.x;
        xs_hi[r * XS_STRIDE + 2 * l + 1] = vh.y;
        xs_lo[r * XS_STRIDE + 2 * l]     = vl.x;
        xs_lo[r * XS_STRIDE + 2 * l + 1] = vl.y;
    }
    __syncthreads();

    int m0 = (wid >> 1) * 16;          // warp row base within tile
    int nh = (wid & 1) * 8;            // warp n-tile base (8 tiles of 8 cols)
    int g = lane >> 2, tig = lane & 3;

    float acc[8][4];
    #pragma unroll
    for (int t = 0; t < 8; t++)
        #pragma unroll
        for (int i = 0; i < 4; i++) acc[t][i] = 0.f;

    #pragma unroll
    for (int kt = 0; kt < 8; kt++) {
        // A fragments (m16k16): a0/a2 row g, a1/a3 row g+8; pairs +0 / +4
        int base = kt * 8 + tig;
        unsigned ahi[4], alo[4];
        ahi[0] = xs_hi[(m0 + g) * XS_STRIDE + base];
        ahi[1] = xs_hi[(m0 + g + 8) * XS_STRIDE + base];
        ahi[2] = xs_hi[(m0 + g) * XS_STRIDE + base + 4];
        ahi[3] = xs_hi[(m0 + g + 8) * XS_STRIDE + base + 4];
        alo[0] = xs_lo[(m0 + g) * XS_STRIDE + base];
        alo[1] = xs_lo[(m0 + g + 8) * XS_STRIDE + base];
        alo[2] = xs_lo[(m0 + g) * XS_STRIDE + base + 4];
        alo[3] = xs_lo[(m0 + g + 8) * XS_STRIDE + base + 4];

        #pragma unroll
        for (int t = 0; t < 8; t++) {
            uint4 w4 = wf[((nh + t) * 8 + kt) * 32 + lane];
            mma_bf16(acc[t], ahi, w4.x, w4.y);   // hi*hi
            mma_bf16(acc[t], ahi, w4.z, w4.w);   // hi*lo
            mma_bf16(acc[t], alo, w4.x, w4.y);   // lo*hi
        }
    }

    // ---- epilogue: bias + LeakyReLU ----
    int r0 = row0 + m0 + g;
    #pragma unroll
    for (int t = 0; t < 8; t++) {
        int col = (nh + t) * 8 + 2 * tig;
        float bb0 = bs[col], bb1 = bs[col + 1];
        float v0 = acc[t][0] + bb0, v1 = acc[t][1] + bb1;
        float v2 = acc[t][2] + bb0, v3 = acc[t][3] + bb1;
        v0 = v0 > 0.f ? v0 : 0.01f * v0;
        v1 = v1 > 0.f ? v1 : 0.01f * v1;
        v2 = v2 > 0.f ? v2 : 0.01f * v2;
        v3 = v3 > 0.f ? v3 : 0.01f * v3;
        if (r0 < n_nodes)
            *reinterpret_cast<float2*>(out + (long)r0 * D + col) = make_float2(v0, v1);
        if (r0 + 8 < n_nodes)
            *reinterpret_cast<float2*>(out + (long)(r0 + 8) * D + col) = make_float2(v2, v3);
    }
}

// ---------------------------------------------------------------------------
extern "C" void kernel_launch(void* const* d_in, const int* in_sizes, int n_in,
                              void* d_out, int out_size) {
    const float* ego = (const float*)d_in[0];
    const void*  ei  = d_in[1];
    const float* ew  = (const float*)d_in[2];
    const float* W   = (const float*)d_in[3];
    const float* b   = (const float*)d_in[4];
    float*       out = (float*)d_out;

    int n_nodes = in_sizes[0] / D;
    int n_edges = in_sizes[2];
    if (n_edges > MAX_EDGES) n_edges = MAX_EDGES;

    int n_samples = n_edges < 64 ? n_edges : 64;
    detect_idx_dtype_kernel<<<1, 32>>>((const unsigned long long*)ei, n_samples);

    zero_counts_kernel<<<(n_nodes + 255) / 256, 256>>>(n_nodes);
    count_kernel<<<(n_edges + 255) / 256, 256>>>(ei, n_edges, n_nodes);
    offsets_kernel<<<(n_nodes + 1023) / 1024, 1024>>>(n_nodes);
    fill_kernel<<<(n_edges + 255) / 256, 256>>>(ei, ew, n_edges, n_nodes);

    aggregate_kernel<<<(n_nodes + 7) / 8, 256>>>((const float4*)ego, n_nodes);

    // smem: wf 64KB + xs_hi 17KB + xs_lo 17KB + bias 0.5KB ~= 98.5KB -> 2 CTA/SM
    size_t smem = (16384 + 2 * 64 * XS_STRIDE) * sizeof(unsigned) + D * sizeof(float);
    cudaFuncSetAttribute(gemm_bf16_kernel,
                         cudaFuncAttributeMaxDynamicSharedMemorySize, (int)smem);
    gemm_bf16_kernel<<<(n_nodes + 63) / 64, 256, smem>>>(W, b, out, n_nodes);
}

// round 12
// speedup vs baseline: 1.5574x; 1.3328x over previous
#include <cuda_runtime.h>
#include <cuda_bf16.h>
#include <cuda_fp16.h>
#include <cstdint>

#define D 128
#define MAX_NODES 100000
#define MAX_EDGES 1600000

// ---- scratch (__device__ globals; no allocs allowed) ----
__device__ uint2  g_xhi[MAX_NODES * 32];         // x hi bf16 pairs, 25.6 MB
__device__ uint2  g_xlo[MAX_NODES * 32];         // x lo bf16 pairs, 25.6 MB
__device__ uint2  g_egoh[MAX_NODES * 32];        // ego as fp16 (4 halves/lane), 25.6 MB
__device__ uint2  g_edges[MAX_EDGES];            // per-node {src, w-bits}, 12.8 MB
__device__ int    g_counts[MAX_NODES];
__device__ int    g_offsets[MAX_NODES];
__device__ int    g_cursor[MAX_NODES];
__device__ int    g_total;
__device__ int    g_idx_is32;

// ---------------------------------------------------------------------------
// K0: detect edge_index dtype. int64 indices < 1e5 -> high word always 0.
// Any nonzero high word in 64 samples => buffer is int32 pairs.
// ---------------------------------------------------------------------------
__global__ void detect_idx_dtype_kernel(const unsigned long long* __restrict__ ei,
                                        int n_samples) {
    if (threadIdx.x == 0) {
        int saw_high = 0;
        for (int i = 0; i < n_samples; i++)
            if (ei[i] >> 32) { saw_high = 1; break; }
        g_idx_is32 = saw_high;
    }
}

// K1: zero counts + total
__global__ void zero_counts_kernel(int n_nodes) {
    int i = blockIdx.x * blockDim.x + threadIdx.x;
    if (i < n_nodes) g_counts[i] = 0;
    if (i == 0) g_total = 0;
}

// K2: histogram of dst degrees
__global__ void count_kernel(const void* __restrict__ ei, int n_edges, int n_nodes) {
    int e = blockIdx.x * blockDim.x + threadIdx.x;
    if (e >= n_edges) return;
    long long dst = g_idx_is32 ? (long long)((const int*)ei)[e]
                               : ((const long long*)ei)[e];
    if ((unsigned long long)dst < (unsigned long long)n_nodes)
        atomicAdd(&g_counts[dst], 1);
}

// K3: per-node segment offsets. Block-local scan + one global atomicAdd per
// block for the base (segment disjointness is order-independent).
__global__ void offsets_kernel(int n_nodes) {
    __shared__ int warp_sums[32];
    __shared__ int block_base;
    int i = blockIdx.x * 1024 + threadIdx.x;
    int lane = threadIdx.x & 31, wid = threadIdx.x >> 5;

    int c = (i < n_nodes) ? g_counts[i] : 0;
    int x = c;
    #pragma unroll
    for (int d = 1; d < 32; d <<= 1) {
        int y = __shfl_up_sync(0xFFFFFFFFu, x, d);
        if (lane >= d) x += y;
    }
    if (lane == 31) warp_sums[wid] = x;
    __syncthreads();
    if (wid == 0) {
        int s = warp_sums[lane];
        #pragma unroll
        for (int d = 1; d < 32; d <<= 1) {
            int y = __shfl_up_sync(0xFFFFFFFFu, s, d);
            if (lane >= d) s += y;
        }
        warp_sums[lane] = s;
        if (lane == 31) block_base = atomicAdd(&g_total, s);
    }
    __syncthreads();
    int warp_base = (wid > 0) ? warp_sums[wid - 1] : 0;
    int excl = block_base + warp_base + (x - c);
    if (i < n_nodes) { g_offsets[i] = excl; g_cursor[i] = excl; }
}

// K4: scatter edges into per-node segments
__global__ void fill_kernel(const void* __restrict__ ei,
                            const float* __restrict__ ew,
                            int n_edges, int n_nodes) {
    int e = blockIdx.x * blockDim.x + threadIdx.x;
    if (e >= n_edges) return;
    long long dst, src;
    if (g_idx_is32) {
        dst = (long long)((const int*)ei)[e];
        src = (long long)((const int*)ei)[n_edges + e];
    } else {
        dst = ((const long long*)ei)[e];
        src = ((const long long*)ei)[n_edges + e];
    }
    if ((unsigned long long)dst >= (unsigned long long)n_nodes ||
        (unsigned long long)src >= (unsigned long long)n_nodes) return;
    int pos = atomicAdd(&g_cursor[dst], 1);
    if (pos < MAX_EDGES)
        g_edges[pos] = make_uint2((unsigned)src, __float_as_uint(ew[e]));
}

// K4b: convert ego -> fp16 (halves gather traffic in the aggregate)
__global__ void convert_ego_kernel(const float4* __restrict__ ego4, int n4) {
    int i = blockIdx.x * blockDim.x + threadIdx.x;
    if (i >= n4) return;
    float4 v = ego4[i];
    __half2 h01 = __floats2half2_rn(v.x, v.y);
    __half2 h23 = __floats2half2_rn(v.z, v.w);
    g_egoh[i] = make_uint2(*reinterpret_cast<unsigned*>(&h01),
                           *reinterpret_cast<unsigned*>(&h23));
}

// ---------------------------------------------------------------------------
// K5: gather-aggregate (fp16 messages, fp32 accumulation + self row) and
// bf16 hi/lo split emit for the tensor GEMM.
// ---------------------------------------------------------------------------
__device__ __forceinline__ unsigned pack_bf16(float a, float b) {
    __nv_bfloat162 t = __floats2bfloat162_rn(a, b);
    return *reinterpret_cast<unsigned*>(&t);
}

__device__ __forceinline__ void acc_h(float4& acc, uint2 q, float w) {
    __half2 h01 = *reinterpret_cast<__half2*>(&q.x);
    __half2 h23 = *reinterpret_cast<__half2*>(&q.y);
    float2 f01 = __half22float2(h01);
    float2 f23 = __half22float2(h23);
    acc.x += f01.x * w; acc.y += f01.y * w;
    acc.z += f23.x * w; acc.w += f23.y * w;
}

__global__ __launch_bounds__(256)
void aggregate_kernel(const float4* __restrict__ ego4, int n_nodes) {
    int warp = (blockIdx.x * blockDim.x + threadIdx.x) >> 5;
    int lane = threadIdx.x & 31;
    if (warp >= n_nodes) return;

    int off = g_offsets[warp];
    int deg = g_counts[warp];

    float4 acc = ego4[(long)warp * 32 + lane];   // self row, fp32

    int e = 0;
    for (; e + 4 <= deg; e += 4) {
        uint2 p0 = g_edges[off + e + 0];
        uint2 p1 = g_edges[off + e + 1];
        uint2 p2 = g_edges[off + e + 2];
        uint2 p3 = g_edges[off + e + 3];
        uint2 q0 = g_egoh[(long)p0.x * 32 + lane];
        uint2 q1 = g_egoh[(long)p1.x * 32 + lane];
        uint2 q2 = g_egoh[(long)p2.x * 32 + lane];
        uint2 q3 = g_egoh[(long)p3.x * 32 + lane];
        acc_h(acc, q0, __uint_as_float(p0.y));
        acc_h(acc, q1, __uint_as_float(p1.y));
        acc_h(acc, q2, __uint_as_float(p2.y));
        acc_h(acc, q3, __uint_as_float(p3.y));
    }
    for (; e < deg; e++) {
        uint2 p = g_edges[off + e];
        uint2 q = g_egoh[(long)p.x * 32 + lane];
        acc_h(acc, q, __uint_as_float(p.y));
    }

    // hi/lo bf16 split (hi = round, lo = bf16(residual))
    __nv_bfloat162 h01 = __floats2bfloat162_rn(acc.x, acc.y);
    __nv_bfloat162 h23 = __floats2bfloat162_rn(acc.z, acc.w);
    float lx = acc.x - __bfloat162float(h01.x);
    float ly = acc.y - __bfloat162float(h01.y);
    float lz = acc.z - __bfloat162float(h23.x);
    float lw = acc.w - __bfloat162float(h23.y);

    g_xhi[(long)warp * 32 + lane] =
        make_uint2(*reinterpret_cast<unsigned*>(&h01), *reinterpret_cast<unsigned*>(&h23));
    g_xlo[(long)warp * 32 + lane] = make_uint2(pack_bf16(lx, ly), pack_bf16(lz, lw));
}

// ---------------------------------------------------------------------------
// K6: persistent bf16 tensor GEMM: out = LeakyReLU(x @ W^T + b), 3-pass hi/lo.
// W fragment table staged ONCE per CTA; grid-stride loop over 64-row x tiles.
// Warp grid 4(m) x 2(n); mainloop = 1 LDS.128 + 3 HMMA per n-tile.
// ---------------------------------------------------------------------------
#define XS_STRIDE 68   // u32 (k-pair) stride: bank = 4*row + pair -> conflict-free

__device__ __forceinline__ void mma_bf16(float* c, const unsigned* a,
                                         unsigned b0, unsigned b1) {
    asm volatile(
        "mma.sync.aligned.m16n8k16.row.col.f32.bf16.bf16.f32 "
        "{%0,%1,%2,%3}, {%4,%5,%6,%7}, {%8,%9}, {%0,%1,%2,%3};"
        : "+f"(c[0]), "+f"(c[1]), "+f"(c[2]), "+f"(c[3])
        : "r"(a[0]), "r"(a[1]), "r"(a[2]), "r"(a[3]), "r"(b0), "r"(b1));
}

__global__ __launch_bounds__(256, 2)
void gemm_bf16_kernel(const float* __restrict__ W,
                      const float* __restrict__ b,
                      float* __restrict__ out, int n_nodes, int n_tiles) {
    extern __shared__ unsigned smu[];
    uint4*    wf    = reinterpret_cast<uint4*>(smu);       // [16 t][8 kt][32 l] {hi01,hi89,lo01,lo89}
    unsigned* xs_hi = smu + 16384;                         // [64][XS_STRIDE]
    unsigned* xs_lo = xs_hi + 64 * XS_STRIDE;
    float*    bs    = reinterpret_cast<float*>(xs_lo + 64 * XS_STRIDE);  // [128]

    int tid = threadIdx.x;
    int lane = tid & 31, wid = tid >> 5;

    // ---- stage W fragments once per CTA ----
    for (int e = tid; e < 4096; e += 256) {
        int t = e >> 8, kt = (e >> 5) & 7, l = e & 31;
        int n = t * 8 + (l >> 2);
        int k0 = kt * 16 + (l & 3) * 2;
        const float* wr = W + n * D + k0;
        float f0 = wr[0], f1 = wr[1], f8 = wr[8], f9 = wr[9];
        __nv_bfloat162 h01 = __floats2bfloat162_rn(f0, f1);
        __nv_bfloat162 h89 = __floats2bfloat162_rn(f8, f9);
        unsigned hi01 = *reinterpret_cast<unsigned*>(&h01);
        unsigned hi89 = *reinterpret_cast<unsigned*>(&h89);
        unsigned lo01 = pack_bf16(f0 - __bfloat162float(h01.x), f1 - __bfloat162float(h01.y));
        unsigned lo89 = pack_bf16(f8 - __bfloat162float(h89.x), f9 - __bfloat162float(h89.y));
        wf[e] = make_uint4(hi01, hi89, lo01, lo89);
    }
    if (tid < D) bs[tid] = b[tid];

    int m0 = (wid >> 1) * 16;
    int nh = (wid & 1) * 8;
    int g = lane >> 2, tig = lane & 3;

    for (int tile = blockIdx.x; tile < n_tiles; tile += gridDim.x) {
        int row0 = tile * 64;
        __syncthreads();   // protect xs from previous iteration's readers

        for (int idx = tid; idx < 64 * 32; idx += 256) {
            int r = idx >> 5, l = idx & 31;
            int row = row0 + r;
            uint2 vh = make_uint2(0u, 0u), vl = make_uint2(0u, 0u);
            if (row < n_nodes) {
                vh = g_xhi[(long)row * 32 + l];
                vl = g_xlo[(long)row * 32 + l];
            }
            xs_hi[r * XS_STRIDE + 2 * l]     = vh.x;
            xs_hi[r * XS_STRIDE + 2 * l + 1] = vh.y;
            xs_lo[r * XS_STRIDE + 2 * l]     = vl.x;
            xs_lo[r * XS_STRIDE + 2 * l + 1] = vl.y;
        }
        __syncthreads();

        float acc[8][4];
        #pragma unroll
        for (int t = 0; t < 8; t++)
            #pragma unroll
            for (int i = 0; i < 4; i++) acc[t][i] = 0.f;

        #pragma unroll
        for (int kt = 0; kt < 8; kt++) {
            int base = kt * 8 + tig;
            unsigned ahi[4], alo[4];
            ahi[0] = xs_hi[(m0 + g) * XS_STRIDE + base];
            ahi[1] = xs_hi[(m0 + g + 8) * XS_STRIDE + base];
            ahi[2] = xs_hi[(m0 + g) * XS_STRIDE + base + 4];
            ahi[3] = xs_hi[(m0 + g + 8) * XS_STRIDE + base + 4];
            alo[0] = xs_lo[(m0 + g) * XS_STRIDE + base];
            alo[1] = xs_lo[(m0 + g + 8) * XS_STRIDE + base];
            alo[2] = xs_lo[(m0 + g) * XS_STRIDE + base + 4];
            alo[3] = xs_lo[(m0 + g + 8) * XS_STRIDE + base + 4];

            #pragma unroll
            for (int t = 0; t < 8; t++) {
                uint4 w4 = wf[((nh + t) * 8 + kt) * 32 + lane];
                mma_bf16(acc[t], ahi, w4.x, w4.y);   // hi*hi
                mma_bf16(acc[t], ahi, w4.z, w4.w);   // hi*lo
                mma_bf16(acc[t], alo, w4.x, w4.y);   // lo*hi
            }
        }

        int r0 = row0 + m0 + g;
        #pragma unroll
        for (int t = 0; t < 8; t++) {
            int col = (nh + t) * 8 + 2 * tig;
            float bb0 = bs[col], bb1 = bs[col + 1];
            float v0 = acc[t][0] + bb0, v1 = acc[t][1] + bb1;
            float v2 = acc[t][2] + bb0, v3 = acc[t][3] + bb1;
            v0 = v0 > 0.f ? v0 : 0.01f * v0;
            v1 = v1 > 0.f ? v1 : 0.01f * v1;
            v2 = v2 > 0.f ? v2 : 0.01f * v2;
            v3 = v3 > 0.f ? v3 : 0.01f * v3;
            if (r0 < n_nodes)
                *reinterpret_cast<float2*>(out + (long)r0 * D + col) = make_float2(v0, v1);
            if (r0 + 8 < n_nodes)
                *reinterpret_cast<float2*>(out + (long)(r0 + 8) * D + col) = make_float2(v2, v3);
        }
    }
}

// ---------------------------------------------------------------------------
extern "C" void kernel_launch(void* const* d_in, const int* in_sizes, int n_in,
                              void* d_out, int out_size) {
    const float* ego = (const float*)d_in[0];
    const void*  ei  = d_in[1];
    const float* ew  = (const float*)d_in[2];
    const float* W   = (const float*)d_in[3];
    const float* b   = (const float*)d_in[4];
    float*       out = (float*)d_out;

    int n_nodes = in_sizes[0] / D;
    int n_edges = in_sizes[2];
    if (n_edges > MAX_EDGES) n_edges = MAX_EDGES;

    int n_samples = n_edges < 64 ? n_edges : 64;
    detect_idx_dtype_kernel<<<1, 32>>>((const unsigned long long*)ei, n_samples);

    zero_counts_kernel<<<(n_nodes + 255) / 256, 256>>>(n_nodes);
    count_kernel<<<(n_edges + 255) / 256, 256>>>(ei, n_edges, n_nodes);
    offsets_kernel<<<(n_nodes + 1023) / 1024, 1024>>>(n_nodes);
    fill_kernel<<<(n_edges + 255) / 256, 256>>>(ei, ew, n_edges, n_nodes);

    int n4 = n_nodes * 32;
    convert_ego_kernel<<<(n4 + 255) / 256, 256>>>((const float4*)ego, n4);

    aggregate_kernel<<<(n_nodes + 7) / 8, 256>>>((const float4*)ego, n_nodes);

    // Persistent GEMM: 2 CTAs/SM x 148 SMs
    int n_tiles = (n_nodes + 63) / 64;
    int gblocks = 296 < n_tiles ? 296 : n_tiles;
    size_t smem = (16384 + 2 * 64 * XS_STRIDE) * sizeof(unsigned) + D * sizeof(float);
    cudaFuncSetAttribute(gemm_bf16_kernel,
                         cudaFuncAttributeMaxDynamicSharedMemorySize, (int)smem);
    gemm_bf16_kernel<<<gblocks, 256, smem>>>(W, b, out, n_nodes, n_tiles);
}